// round 15
// baseline (speedup 1.0000x reference)
#include <cuda_runtime.h>
#include <cuda_fp16.h>
#include <cstdint>

// ---------------- problem constants ----------------
#define EMB   192
#define D0    128
#define D1    256
#define D2    128
#define NC    32
#define NT    4
#define NY    50000
#define NX    32768
#define KNB   8
#define NE    (NX*KNB)
#define MT    128
#define NTILES (NE/MT)

// ---------------- global scratch ----------------
__device__ float    g_Ay[NY*D0];
__device__ float    g_Ax[NX*D0];
__device__ uint32_t g_W1img[D0*D1/2];   // fp16x2 frag-ordered (16K u32)
__device__ uint32_t g_W2img[D1*D2/2];   // 16K u32
__device__ uint32_t g_W3img[D2*NC/2];   // 2K u32

// ---------------- math ----------------
__device__ __forceinline__ uint32_t pack_h2(float lo, float hi){
    uint32_t r;
    asm("cvt.rn.f16x2.f32 %0, %1, %2;" : "=r"(r) : "f"(hi), "f"(lo));
    return r;
}
// packed gelu: 2 values per call. 4 h2-ops + 1 MUFU.
__device__ __forceinline__ uint32_t gelu_h2(uint32_t xu){
    __half2 x = *reinterpret_cast<__half2*>(&xu);
    const __half2 c1 = __float2half2_rn(0.7978845608f);
    const __half2 c2 = __float2half2_rn(0.0356774081f);
    __half2 u = __hmul2(x, __hfma2(__hmul2(x, x), c2, c1));
    uint32_t uu = *reinterpret_cast<uint32_t*>(&u), tt;
    asm("tanh.approx.f16x2 %0, %1;" : "=r"(tt) : "r"(uu));
    __half2 t  = *reinterpret_cast<__half2*>(&tt);
    __half2 hx = __hmul2(x, __float2half2_rn(0.5f));
    __half2 r  = __hfma2(hx, t, hx);
    return *reinterpret_cast<uint32_t*>(&r);
}
__device__ __forceinline__ uint32_t hadd2u(uint32_t a, uint32_t b){
    uint32_t r;
    asm("add.rn.f16x2 %0, %1, %2;" : "=r"(r) : "r"(a), "r"(b));
    return r;
}
__device__ __forceinline__ void mma16(float c[4], const uint4 a, const uint2 b){
    asm volatile(
        "mma.sync.aligned.m16n8k16.row.col.f32.f16.f16.f32 "
        "{%0,%1,%2,%3},{%4,%5,%6,%7},{%8,%9},{%0,%1,%2,%3};"
        : "+f"(c[0]), "+f"(c[1]), "+f"(c[2]), "+f"(c[3])
        : "r"(a.x), "r"(a.y), "r"(a.z), "r"(a.w), "r"(b.x), "r"(b.y));
}

// fp16 A-image u32 index, [128 rows x W cols], W/16 ktiles, 8 mtiles.
__device__ __forceinline__ int aidx(int row, int col){
    int tile = (col >> 4)*8 + (row >> 4);
    int lane = (row & 7)*4 + ((col & 7) >> 1);
    int reg  = ((row >> 3) & 1) | (((col >> 3) & 1) << 1);
    return tile*128 + lane*4 + reg;
}

// ---------------- weight prep: fp16 fragment images ----------------
__global__ void wprep_kernel(const float* __restrict__ W1,
                             const float* __restrict__ W2,
                             const float* __restrict__ W3){
    int id = blockIdx.x*blockDim.x + threadIdx.x;
    if (id < 16384){                 // W1 [k=128][n=256]
        int t = id >> 6, u = id & 63, lane = u >> 1, reg = u & 1;
        int nt = t & 7, kt = (t >> 3) & 7, ch = t >> 6;
        int n = ch*64 + nt*8 + (lane >> 2);
        int k = kt*16 + reg*8 + (lane & 3)*2;
        g_W1img[id] = pack_h2(W1[k*D1 + n], W1[(k+1)*D1 + n]);
    } else if (id < 32768){          // W2 [k=256][n=128]
        int j = id - 16384;
        int t = j >> 6, u = j & 63, lane = u >> 1, reg = u & 1;
        int nt = t & 15, kt = (t >> 4) & 3, ch = t >> 6;
        int n = nt*8 + (lane >> 2);
        int k = ch*64 + kt*16 + reg*8 + (lane & 3)*2;
        g_W2img[j] = pack_h2(W2[k*D2 + n], W2[(k+1)*D2 + n]);
    } else if (id < 34816){          // W3 [k=128][n=32]
        int j = id - 32768;
        int t = j >> 6, u = j & 63, lane = u >> 1, reg = u & 1;
        int nt = t & 3, kt = t >> 2;
        int n = nt*8 + (lane >> 2);
        int k = kt*16 + reg*8 + (lane & 3)*2;
        g_W3img[j] = pack_h2(W3[k*NC + n], W3[(k+1)*NC + n]);
    }
}

// ---------------- precompute A_y / A_x via fp16 mma ----------------
#define PRE_SMEM (49152 + 49152 + 512)
__global__ void __launch_bounds__(256)
precompute_kernel(const float* __restrict__ y, const float* __restrict__ x,
                  const float* __restrict__ W0, const float* __restrict__ b0g)
{
    extern __shared__ char psm[];
    uint32_t* sEmb = (uint32_t*)psm;
    uint32_t* sW0  = (uint32_t*)(psm + 49152);
    float*    sb0  = (float*)(psm + 98304);

    const int nyb = (NY + 127)/128;
    const bool isY = (int)blockIdx.x < nyb;
    const int row0  = isY ? blockIdx.x*128 : ((int)blockIdx.x - nyb)*128;
    const int limit = isY ? NY : NX;
    const float* P  = isY ? y : x;
    const float* Wb = isY ? W0 : (W0 + EMB*D0);
    float* outp     = isY ? g_Ay : g_Ax;

    const int tid  = threadIdx.x;
    const int w    = tid >> 5;
    const int lane = tid & 31;
    const int g    = lane >> 2;
    const int q    = lane & 3;

    if (tid < 128) sb0[tid] = isY ? 0.f : b0g[tid];

    for (int idx = tid; idx < 12288; idx += 256){
        int t = idx >> 6, u = idx & 63, ln = u >> 1, reg = u & 1;
        int nt = t & 15, kt = t >> 4;
        int n = nt*8 + (ln >> 2);
        int k = kt*16 + reg*8 + (ln & 3)*2;
        sW0[idx] = pack_h2(Wb[k*D0 + n], Wb[(k+1)*D0 + n]);
    }
    for (int idx = tid; idx < 12288; idx += 256){
        int row = idx / 96, cp = idx - row*96;
        int r = row0 + row; if (r >= limit) r = limit - 1;
        int d = cp >> 5, f = cp & 31;
        float freq = exp2f(-0.41524101186092029f * (float)f);
        float ang = P[r*3 + d] * freq;
        float s, c; __sincosf(ang, &s, &c);
        int tile = (cp >> 3)*8 + (row >> 4);
        int ln   = (row & 7)*4 + (cp & 3);
        int reg  = ((row >> 3) & 1) | (((cp >> 2) & 1) << 1);
        sEmb[tile*128 + ln*4 + reg] = pack_h2(s, c);
    }
    __syncthreads();

    float acc[16][4];
#pragma unroll
    for (int nt = 0; nt < 16; nt++)
#pragma unroll
        for (int r = 0; r < 4; r++) acc[nt][r] = 0.f;

#pragma unroll 3
    for (int kt = 0; kt < 12; kt++){
        uint4 a = *(const uint4*)(sEmb + (kt*8 + w)*128 + lane*4);
#pragma unroll
        for (int nt = 0; nt < 16; nt++){
            uint2 b = *(const uint2*)(sW0 + (kt*16 + nt)*64 + lane*2);
            mma16(acc[nt], a, b);
        }
    }
#pragma unroll
    for (int nt = 0; nt < 16; nt++){
        int c0 = nt*8 + 2*q;
        int r  = w*16 + g;
        if (row0 + r < limit){
            float2 v = make_float2(acc[nt][0] + sb0[c0], acc[nt][1] + sb0[c0+1]);
            *(float2*)(outp + (size_t)(row0 + r)*D0 + c0) = v;
        }
        if (row0 + r + 8 < limit){
            float2 v = make_float2(acc[nt][2] + sb0[c0], acc[nt][3] + sb0[c0+1]);
            *(float2*)(outp + (size_t)(row0 + r + 8)*D0 + c0) = v;
        }
    }
}

// ---------------- persistent fused edge kernel (fp16 mma, 1024 thr) ------
// smem: sH1 32KB @0 | buf 32KB @32768 (also s_kern) | sW1 64KB @65536 |
//       sW2 64KB @131072 | sW3 8KB @196608 | misc @204800
#define OFF_H1   0
#define OFF_H2   32768
#define OFF_W1   65536
#define OFF_W2   131072
#define OFF_W3   196608
#define OFF_MISC 204800
#define SMEM_BYTES (204800 + 1536)

// gather one tile: h1 = gelu(A_y[nbr] + A_x) -> fp16 frag image + s_nbr
__device__ __forceinline__ void do_gather(uint32_t* sH1, int* s_nbr,
                                          const int* __restrict__ nbr,
                                          int e0, int xbase, int tid)
{
    if (tid < 128) s_nbr[tid] = nbr[e0 + tid];
    const int p   = tid & 63;          // col pair (cols 2p, 2p+1)
    const int grp = tid >> 6;          // 16 groups x 8 edges
    const float* ax = g_Ax + (size_t)xbase*D0 + 2*p;
#pragma unroll 4
    for (int i = 0; i < 8; i++){
        int e = grp*8 + i;
        int ne = nbr[e0 + e];
        float2 ay = *(const float2*)(g_Ay + (size_t)ne*D0 + 2*p);
        float2 axv = *(const float2*)(ax + (e >> 3)*D0);
        int tilei = (p >> 3)*8 + (e >> 4);
        int ln    = (e & 7)*4 + (p & 3);
        int reg   = ((e >> 3) & 1) | (((p >> 2) & 1) << 1);
        sH1[tilei*128 + ln*4 + reg] =
            gelu_h2(pack_h2(ay.x + axv.x, ay.y + axv.y));
    }
}

__global__ void __launch_bounds__(1024, 1)
edge_kernel(const int* __restrict__ nbr, const float* __restrict__ fy,
            const float* __restrict__ b1g, const float* __restrict__ b2g,
            const float* __restrict__ b3g, float* __restrict__ out)
{
    extern __shared__ char sm[];
    uint32_t* sH1 = (uint32_t*)(sm + OFF_H1);
    uint32_t* buf = (uint32_t*)(sm + OFF_H2);   // 128x128 h2 image (32 KB)
    uint32_t* sW1 = (uint32_t*)(sm + OFF_W1);
    uint32_t* sW2 = (uint32_t*)(sm + OFF_W2);
    uint32_t* sW3 = (uint32_t*)(sm + OFF_W3);
    int*      s_nbr = (int*)(sm + OFF_MISC);                 // 128 ints
    uint32_t* sb1h  = (uint32_t*)(sm + OFF_MISC + 512);      // 128 h2 pairs
    uint32_t* sb2h  = (uint32_t*)(sm + OFF_MISC + 1024);     // 64 h2 pairs
    float*    sb3   = (float*)(sm + OFF_MISC + 1280);        // 32 fp32

    const int tid  = threadIdx.x;
    const int w    = tid >> 5;         // 0..31
    const int lane = tid & 31;
    const int g    = lane >> 2;
    const int q    = lane & 3;
    const int wr2  = w >> 3;           // 32-row strip 0..3 (GEMM1/2)
    const int wc2  = w & 7;            // 16-col group 0..7
    const int wr3  = w >> 2;           // GEMM3: 16-row strip 0..7
    const int wc3  = w & 3;            // GEMM3: 8-col group 0..3

    // ---- stage ALL weights + biases once per CTA ----
    {
        const uint4* s1 = (const uint4*)g_W1img;  uint4* d1 = (uint4*)sW1;
        const uint4* s2 = (const uint4*)g_W2img;  uint4* d2 = (uint4*)sW2;
        const uint4* s3 = (const uint4*)g_W3img;  uint4* d3 = (uint4*)sW3;
        for (int i = tid; i < 4096; i += 1024) d1[i] = s1[i];
        for (int i = tid; i < 4096; i += 1024) d2[i] = s2[i];
        for (int i = tid; i < 512;  i += 1024) d3[i] = s3[i];
        if (tid < 128) sb1h[tid] = pack_h2(b1g[2*tid], b1g[2*tid + 1]);
        else if (tid < 192) sb2h[tid - 128] = pack_h2(b2g[2*(tid-128)], b2g[2*(tid-128) + 1]);
        else if (tid < 224) sb3[tid - 192] = b3g[tid - 192];
    }
    __syncthreads();

    // ---- prologue: gather tile 0 ----
    int tile = blockIdx.x;
    if (tile < NTILES)
        do_gather(sH1, s_nbr, nbr, tile*MT, tile*(MT/KNB), tid);

    for (; tile < NTILES; tile += gridDim.x){
        const int xbase = tile * (MT/KNB);
        __syncthreads();               // sH1 + s_nbr of this tile ready

        float acc2[2][2][4];
#pragma unroll
        for (int m = 0; m < 2; m++)
#pragma unroll
            for (int n = 0; n < 2; n++)
#pragma unroll
                for (int r = 0; r < 4; r++) acc2[m][n][r] = 0.f;

        // ---- sweep loop over D1 (2 sweeps of 128 cols) ----
        for (int h = 0; h < 2; h++){
            // GEMM1: h2s[128x128] = h1 @ W1[:, h*128..]; warp: 32 rows x 16 cols
            float acc1[2][2][4];
#pragma unroll
            for (int m = 0; m < 2; m++)
#pragma unroll
                for (int n = 0; n < 2; n++)
#pragma unroll
                    for (int r = 0; r < 4; r++) acc1[m][n][r] = 0.f;

#pragma unroll 2
            for (int kt = 0; kt < 8; kt++){
                uint4 a0 = *(const uint4*)(sH1 + (kt*8 + 2*wr2    )*128 + lane*4);
                uint4 a1 = *(const uint4*)(sH1 + (kt*8 + 2*wr2 + 1)*128 + lane*4);
#pragma unroll
                for (int nt = 0; nt < 2; nt++){
                    int gn = h*16 + wc2*2 + nt;            // global 8-col tile
                    uint2 b = *(const uint2*)(sW1 + (((gn >> 3)*8 + kt)*8 + (gn & 7))*64 + lane*2);
                    mma16(acc1[0][nt], a0, b);
                    mma16(acc1[1][nt], a1, b);
                }
            }
            // epilogue1 -> buf (local cols of this sweep)
            {
#pragma unroll
                for (int m = 0; m < 2; m++){
                    int r0 = 32*wr2 + 16*m + g;
#pragma unroll
                    for (int nt = 0; nt < 2; nt++){
                        int lc = wc2*16 + nt*8 + 2*q;
                        uint32_t bb = sb1h[(h*128 + lc) >> 1];
                        buf[aidx(r0,     lc)] = gelu_h2(hadd2u(
                            pack_h2(acc1[m][nt][0], acc1[m][nt][1]), bb));
                        buf[aidx(r0 + 8, lc)] = gelu_h2(hadd2u(
                            pack_h2(acc1[m][nt][2], acc1[m][nt][3]), bb));
                    }
                }
            }
            __syncthreads();

            // GEMM2 partial: h3 += h2s @ W2[h*128.., :]; warp: 32 rows x 16 cols
#pragma unroll 2
            for (int kt2 = 0; kt2 < 8; kt2++){
                uint4 a0 = *(const uint4*)(buf + (kt2*8 + 2*wr2    )*128 + lane*4);
                uint4 a1 = *(const uint4*)(buf + (kt2*8 + 2*wr2 + 1)*128 + lane*4);
                int gk = h*8 + kt2;                        // global 16-k tile
#pragma unroll
                for (int nt = 0; nt < 2; nt++){
                    int n = wc2*2 + nt;
                    uint2 b = *(const uint2*)(sW2 + (((gk >> 2)*4 + (gk & 3))*16 + n)*64 + lane*2);
                    mma16(acc2[0][nt], a0, b);
                    mma16(acc2[1][nt], a1, b);
                }
            }
            __syncthreads();   // WAR: buf rewritten next sweep (or s_kern later)
        }

        // ---- epilogue2: h3 = gelu(acc2 + b2) -> sH1 image ----
        {
#pragma unroll
            for (int m = 0; m < 2; m++){
                int r0 = 32*wr2 + 16*m + g;
#pragma unroll
                for (int nt = 0; nt < 2; nt++){
                    int cg = wc2*16 + nt*8 + 2*q;
                    uint32_t bb = sb2h[cg >> 1];
                    sH1[aidx(r0,     cg)] = gelu_h2(hadd2u(
                        pack_h2(acc2[m][nt][0], acc2[m][nt][1]), bb));
                    sH1[aidx(r0 + 8, cg)] = gelu_h2(hadd2u(
                        pack_h2(acc2[m][nt][2], acc2[m][nt][3]), bb));
                }
            }
        }
        __syncthreads();

        // ---- f_y prefetch (overlaps GEMM3): needs only s_nbr ----
        const int rr = w & 15;
        const int tb = w >> 4;             // t in {tb, tb+2}
        float fyv[2][8];
#pragma unroll
        for (int t2 = 0; t2 < 2; t2++)
#pragma unroll
            for (int j = 0; j < 8; j++)
                fyv[t2][j] = fy[((size_t)(tb + 2*t2)*NY + s_nbr[rr*8 + j])*NC + lane];

        // ---- GEMM3: kern[128x32] = h3 @ W3; warp: 16 rows x 8 cols ----
        float acc3[4];
#pragma unroll
        for (int r = 0; r < 4; r++) acc3[r] = 0.f;
#pragma unroll 2
        for (int kt = 0; kt < 8; kt++){
            uint4 a = *(const uint4*)(sH1 + (kt*8 + wr3)*128 + lane*4);
            uint2 b = *(const uint2*)(sW3 + (kt*4 + wc3)*64 + lane*2);
            mma16(acc3, a, b);
        }
        float* s_kern = (float*)(sm + OFF_H2);    // 128x33 fp32 (over buf)
        {
            int r0 = 16*wr3 + g;
            int c  = wc3*8 + 2*q;
            float bb0 = sb3[c], bb1 = sb3[c + 1];
            s_kern[r0*33 + c]           = acc3[0] + bb0;
            s_kern[r0*33 + c + 1]       = acc3[1] + bb1;
            s_kern[(r0 + 8)*33 + c]     = acc3[2] + bb0;
            s_kern[(r0 + 8)*33 + c + 1] = acc3[3] + bb1;
        }
        __syncthreads();   // s_kern visible; sH1/s_nbr consumers done

        // ---- overlap: gather NEXT tile while reducing this one ----
        int nxt = tile + (int)gridDim.x;
        if (nxt < NTILES)
            do_gather(sH1, s_nbr, nbr, nxt*MT, nxt*(MT/KNB), tid);

        // ---- reduction with prefetched f_y ----
#pragma unroll
        for (int t2 = 0; t2 < 2; t2++){
            float acc = 0.f;
#pragma unroll
            for (int j = 0; j < 8; j++)
                acc = fmaf(s_kern[(rr*8 + j)*33 + lane], fyv[t2][j], acc);
            out[((size_t)(tb + 2*t2)*NX + xbase + rr)*NC + lane] = acc;
        }
        // no tail barrier: top-of-loop __syncthreads covers sH1/s_nbr/buf
    }
}

// ---------------- launch ----------------
extern "C" void kernel_launch(void* const* d_in, const int* in_sizes, int n_in,
                              void* d_out, int out_size)
{
    const float* y  = (const float*)d_in[0];
    const float* x  = (const float*)d_in[1];
    const float* fy = (const float*)d_in[2];
    const int*   nbr = (const int*)d_in[3];
    const float* W0 = (const float*)d_in[4];  const float* b0 = (const float*)d_in[5];
    const float* W1 = (const float*)d_in[6];  const float* b1 = (const float*)d_in[7];
    const float* W2 = (const float*)d_in[8];  const float* b2 = (const float*)d_in[9];
    const float* W3 = (const float*)d_in[10]; const float* b3 = (const float*)d_in[11];
    float* out = (float*)d_out;

    wprep_kernel<<<136, 256>>>(W1, W2, W3);

    int nyb = (NY + 127)/128, nxb = (NX + 127)/128;
    cudaFuncSetAttribute(precompute_kernel,
                         cudaFuncAttributeMaxDynamicSharedMemorySize, PRE_SMEM);
    precompute_kernel<<<nyb + nxb, 256, PRE_SMEM>>>(y, x, W0, b0);

    cudaFuncSetAttribute(edge_kernel,
                         cudaFuncAttributeMaxDynamicSharedMemorySize, SMEM_BYTES);
    edge_kernel<<<152, 1024, SMEM_BYTES>>>(nbr, fy, b1, b2, b3, out);
}

// round 16
// speedup vs baseline: 1.0419x; 1.0419x over previous
#include <cuda_runtime.h>
#include <cuda_fp16.h>
#include <cstdint>

// ---------------- problem constants ----------------
#define EMB   192
#define D0    128
#define D1    256
#define D2    128
#define NC    32
#define NT    4
#define NY    50000
#define NX    32768
#define KNB   8
#define NE    (NX*KNB)
#define MT    128
#define NTILES (NE/MT)

// ---------------- global scratch ----------------
__device__ float    g_Ay[NY*D0];
__device__ float    g_Ax[NX*D0];
__device__ uint32_t g_W1img[D0*D1/2];   // fp16x2 frag-ordered (16K u32)
__device__ uint32_t g_W2img[D1*D2/2];   // 16K u32
__device__ uint32_t g_W3img[D2*NC/2];   // 2K u32

// ---------------- math ----------------
__device__ __forceinline__ uint32_t pack_h2(float lo, float hi){
    uint32_t r;
    asm("cvt.rn.f16x2.f32 %0, %1, %2;" : "=r"(r) : "f"(hi), "f"(lo));
    return r;
}
// packed gelu: 2 values per call. 4 h2-ops + 1 MUFU.
__device__ __forceinline__ uint32_t gelu_h2(uint32_t xu){
    __half2 x = *reinterpret_cast<__half2*>(&xu);
    const __half2 c1 = __float2half2_rn(0.7978845608f);
    const __half2 c2 = __float2half2_rn(0.0356774081f);
    __half2 u = __hmul2(x, __hfma2(__hmul2(x, x), c2, c1));
    uint32_t uu = *reinterpret_cast<uint32_t*>(&u), tt;
    asm("tanh.approx.f16x2 %0, %1;" : "=r"(tt) : "r"(uu));
    __half2 t  = *reinterpret_cast<__half2*>(&tt);
    __half2 hx = __hmul2(x, __float2half2_rn(0.5f));
    __half2 r  = __hfma2(hx, t, hx);
    return *reinterpret_cast<uint32_t*>(&r);
}
__device__ __forceinline__ uint32_t hadd2u(uint32_t a, uint32_t b){
    uint32_t r;
    asm("add.rn.f16x2 %0, %1, %2;" : "=r"(r) : "r"(a), "r"(b));
    return r;
}
__device__ __forceinline__ void mma16(float c[4], const uint4 a, const uint2 b){
    asm volatile(
        "mma.sync.aligned.m16n8k16.row.col.f32.f16.f16.f32 "
        "{%0,%1,%2,%3},{%4,%5,%6,%7},{%8,%9},{%0,%1,%2,%3};"
        : "+f"(c[0]), "+f"(c[1]), "+f"(c[2]), "+f"(c[3])
        : "r"(a.x), "r"(a.y), "r"(a.z), "r"(a.w), "r"(b.x), "r"(b.y));
}

// fp16 A-image u32 index, [128 rows x W cols], W/16 ktiles, 8 mtiles.
__device__ __forceinline__ int aidx(int row, int col){
    int tile = (col >> 4)*8 + (row >> 4);
    int lane = (row & 7)*4 + ((col & 7) >> 1);
    int reg  = ((row >> 3) & 1) | (((col >> 3) & 1) << 1);
    return tile*128 + lane*4 + reg;
}

// ---------------- merged prep + precompute ----------------
// blocks [0, nyb+nxb): A_y/A_x via fp16 mma. blocks [nyb+nxb, +136): weight images.
#define PRE_SMEM (49152 + 49152 + 512)
__global__ void __launch_bounds__(256)
prep_kernel(const float* __restrict__ y, const float* __restrict__ x,
            const float* __restrict__ W0, const float* __restrict__ b0g,
            const float* __restrict__ W1, const float* __restrict__ W2,
            const float* __restrict__ W3)
{
    const int nyb = (NY + 127)/128;
    const int nxb = (NX + 127)/128;
    const int tid = threadIdx.x;

    if ((int)blockIdx.x >= nyb + nxb){
        // ---- weight prep ----
        int id = ((int)blockIdx.x - nyb - nxb)*256 + tid;
        if (id < 16384){                 // W1 [k=128][n=256]
            int t = id >> 6, u = id & 63, lane = u >> 1, reg = u & 1;
            int nt = t & 7, kt = (t >> 3) & 7, ch = t >> 6;
            int n = ch*64 + nt*8 + (lane >> 2);
            int k = kt*16 + reg*8 + (lane & 3)*2;
            g_W1img[id] = pack_h2(W1[k*D1 + n], W1[(k+1)*D1 + n]);
        } else if (id < 32768){          // W2 [k=256][n=128]
            int j = id - 16384;
            int t = j >> 6, u = j & 63, lane = u >> 1, reg = u & 1;
            int nt = t & 15, kt = (t >> 4) & 3, ch = t >> 6;
            int n = nt*8 + (lane >> 2);
            int k = ch*64 + kt*16 + reg*8 + (lane & 3)*2;
            g_W2img[j] = pack_h2(W2[k*D2 + n], W2[(k+1)*D2 + n]);
        } else if (id < 34816){          // W3 [k=128][n=32]
            int j = id - 32768;
            int t = j >> 6, u = j & 63, lane = u >> 1, reg = u & 1;
            int nt = t & 3, kt = t >> 2;
            int n = nt*8 + (lane >> 2);
            int k = kt*16 + reg*8 + (lane & 3)*2;
            g_W3img[j] = pack_h2(W3[k*NC + n], W3[(k+1)*NC + n]);
        }
        return;
    }

    extern __shared__ char psm[];
    uint32_t* sEmb = (uint32_t*)psm;
    uint32_t* sW0  = (uint32_t*)(psm + 49152);
    float*    sb0  = (float*)(psm + 98304);

    const bool isY = (int)blockIdx.x < nyb;
    const int row0  = isY ? blockIdx.x*128 : ((int)blockIdx.x - nyb)*128;
    const int limit = isY ? NY : NX;
    const float* P  = isY ? y : x;
    const float* Wb = isY ? W0 : (W0 + EMB*D0);
    float* outp     = isY ? g_Ay : g_Ax;

    const int w    = tid >> 5;
    const int lane = tid & 31;
    const int g    = lane >> 2;
    const int q    = lane & 3;

    if (tid < 128) sb0[tid] = isY ? 0.f : b0g[tid];

    for (int idx = tid; idx < 12288; idx += 256){
        int t = idx >> 6, u = idx & 63, ln = u >> 1, reg = u & 1;
        int nt = t & 15, kt = t >> 4;
        int n = nt*8 + (ln >> 2);
        int k = kt*16 + reg*8 + (ln & 3)*2;
        sW0[idx] = pack_h2(Wb[k*D0 + n], Wb[(k+1)*D0 + n]);
    }
    for (int idx = tid; idx < 12288; idx += 256){
        int row = idx / 96, cp = idx - row*96;
        int r = row0 + row; if (r >= limit) r = limit - 1;
        int d = cp >> 5, f = cp & 31;
        float freq = exp2f(-0.41524101186092029f * (float)f);
        float ang = P[r*3 + d] * freq;
        float s, c; __sincosf(ang, &s, &c);
        int tile = (cp >> 3)*8 + (row >> 4);
        int ln   = (row & 7)*4 + (cp & 3);
        int reg  = ((row >> 3) & 1) | (((cp >> 2) & 1) << 1);
        sEmb[tile*128 + ln*4 + reg] = pack_h2(s, c);
    }
    __syncthreads();

    float acc[16][4];
#pragma unroll
    for (int nt = 0; nt < 16; nt++)
#pragma unroll
        for (int r = 0; r < 4; r++) acc[nt][r] = 0.f;

#pragma unroll 3
    for (int kt = 0; kt < 12; kt++){
        uint4 a = *(const uint4*)(sEmb + (kt*8 + w)*128 + lane*4);
#pragma unroll
        for (int nt = 0; nt < 16; nt++){
            uint2 b = *(const uint2*)(sW0 + (kt*16 + nt)*64 + lane*2);
            mma16(acc[nt], a, b);
        }
    }
#pragma unroll
    for (int nt = 0; nt < 16; nt++){
        int c0 = nt*8 + 2*q;
        int r  = w*16 + g;
        if (row0 + r < limit){
            float2 v = make_float2(acc[nt][0] + sb0[c0], acc[nt][1] + sb0[c0+1]);
            *(float2*)(outp + (size_t)(row0 + r)*D0 + c0) = v;
        }
        if (row0 + r + 8 < limit){
            float2 v = make_float2(acc[nt][2] + sb0[c0], acc[nt][3] + sb0[c0+1]);
            *(float2*)(outp + (size_t)(row0 + r + 8)*D0 + c0) = v;
        }
    }
}

// ---------------- persistent fused edge kernel (fp16 mma, 512 thr) -------
// 16 warps, GEMM1/2 grid 4x4 (warp tile 32 rows x 32 cols): A-dup 4, B-dup 4.
// smem: sH1 32KB @0 | buf 32KB @32768 (also s_kern) | sW1 64KB @65536 |
//       sW2 64KB @131072 | sW3 8KB @196608 | misc @204800
#define OFF_H1   0
#define OFF_H2   32768
#define OFF_W1   65536
#define OFF_W2   131072
#define OFF_W3   196608
#define OFF_MISC 204800
#define SMEM_BYTES (204800 + 1536)

__global__ void __launch_bounds__(512, 1)
edge_kernel(const int* __restrict__ nbr, const float* __restrict__ fy,
            const float* __restrict__ b1g, const float* __restrict__ b2g,
            const float* __restrict__ b3g, float* __restrict__ out)
{
    extern __shared__ char sm[];
    uint32_t* sH1 = (uint32_t*)(sm + OFF_H1);
    uint32_t* buf = (uint32_t*)(sm + OFF_H2);   // 128x128 h2 image (32 KB)
    uint32_t* sW1 = (uint32_t*)(sm + OFF_W1);
    uint32_t* sW2 = (uint32_t*)(sm + OFF_W2);
    uint32_t* sW3 = (uint32_t*)(sm + OFF_W3);
    int*      s_nbr = (int*)(sm + OFF_MISC);                 // 128 ints
    uint32_t* sb1h  = (uint32_t*)(sm + OFF_MISC + 512);      // 128 h2 pairs
    uint32_t* sb2h  = (uint32_t*)(sm + OFF_MISC + 1024);     // 64 h2 pairs
    float*    sb3   = (float*)(sm + OFF_MISC + 1280);        // 32 fp32

    const int tid  = threadIdx.x;
    const int w    = tid >> 5;         // 0..15
    const int lane = tid & 31;
    const int g    = lane >> 2;
    const int q    = lane & 3;
    const int wr   = w >> 2;           // 32-row strip 0..3 (GEMM1/2)
    const int wc   = w & 3;            // 32-col group 0..3
    const int wr3  = w >> 1;           // GEMM3: 16-row strip 0..7
    const int wc3  = w & 1;            // GEMM3: 16-col half 0..1

    // ---- stage ALL weights + biases once per CTA ----
    {
        const uint4* s1 = (const uint4*)g_W1img;  uint4* d1 = (uint4*)sW1;
        const uint4* s2 = (const uint4*)g_W2img;  uint4* d2 = (uint4*)sW2;
        const uint4* s3 = (const uint4*)g_W3img;  uint4* d3 = (uint4*)sW3;
        for (int i = tid; i < 4096; i += 512) d1[i] = s1[i];
        for (int i = tid; i < 4096; i += 512) d2[i] = s2[i];
        for (int i = tid; i < 512;  i += 512) d3[i] = s3[i];
        if (tid < 128) sb1h[tid] = pack_h2(b1g[2*tid], b1g[2*tid + 1]);
        else if (tid < 192) sb2h[tid - 128] = pack_h2(b2g[2*(tid-128)], b2g[2*(tid-128) + 1]);
        else if (tid < 224) sb3[tid - 192] = b3g[tid - 192];
    }
    __syncthreads();

    for (int tile = blockIdx.x; tile < NTILES; tile += gridDim.x){
        const int e0    = tile * MT;
        const int xbase = tile * (MT/KNB);

        // ---- gather: h1 = gelu(A_y[nbr] + A_x) -> fp16 frag image ----
        if (tid < 128) s_nbr[tid] = nbr[e0 + tid];
        {
            const int p   = tid & 63;          // col pair (cols 2p, 2p+1)
            const int grp = tid >> 6;          // 8 groups x 16 edges
            const float* ax = g_Ax + (size_t)xbase*D0 + 2*p;
#pragma unroll 4
            for (int i = 0; i < 16; i++){
                int e = grp*16 + i;
                int ne = nbr[e0 + e];
                float2 ay = *(const float2*)(g_Ay + (size_t)ne*D0 + 2*p);
                float2 axv = *(const float2*)(ax + (e >> 3)*D0);
                int tilei = (p >> 3)*8 + (e >> 4);
                int ln    = (e & 7)*4 + (p & 3);
                int reg   = ((e >> 3) & 1) | (((p >> 2) & 1) << 1);
                sH1[tilei*128 + ln*4 + reg] =
                    gelu_h2(pack_h2(ay.x + axv.x, ay.y + axv.y));
            }
        }
        __syncthreads();

        float acc2[2][4][4];
#pragma unroll
        for (int m = 0; m < 2; m++)
#pragma unroll
            for (int n = 0; n < 4; n++)
#pragma unroll
                for (int r = 0; r < 4; r++) acc2[m][n][r] = 0.f;

        // ---- sweep loop over D1 (2 sweeps of 128 cols) ----
        for (int h = 0; h < 2; h++){
            // GEMM1: h2s[128x128] = h1 @ W1[:, h*128..]; warp: 32 rows x 32 cols
            float acc1[2][4][4];
#pragma unroll
            for (int m = 0; m < 2; m++)
#pragma unroll
                for (int n = 0; n < 4; n++)
#pragma unroll
                    for (int r = 0; r < 4; r++) acc1[m][n][r] = 0.f;

#pragma unroll 2
            for (int kt = 0; kt < 8; kt++){
                uint4 a0 = *(const uint4*)(sH1 + (kt*8 + 2*wr    )*128 + lane*4);
                uint4 a1 = *(const uint4*)(sH1 + (kt*8 + 2*wr + 1)*128 + lane*4);
#pragma unroll
                for (int nt = 0; nt < 4; nt++){
                    int gn = h*16 + wc*4 + nt;             // global 8-col tile
                    uint2 b = *(const uint2*)(sW1 + (((gn >> 3)*8 + kt)*8 + (gn & 7))*64 + lane*2);
                    mma16(acc1[0][nt], a0, b);
                    mma16(acc1[1][nt], a1, b);
                }
            }
            // epilogue1 -> buf (local cols of this sweep)
            {
#pragma unroll
                for (int m = 0; m < 2; m++){
                    int r0 = 32*wr + 16*m + g;
#pragma unroll
                    for (int nt = 0; nt < 4; nt++){
                        int lc = wc*32 + nt*8 + 2*q;
                        uint32_t bb = sb1h[(h*128 + lc) >> 1];
                        buf[aidx(r0,     lc)] = gelu_h2(hadd2u(
                            pack_h2(acc1[m][nt][0], acc1[m][nt][1]), bb));
                        buf[aidx(r0 + 8, lc)] = gelu_h2(hadd2u(
                            pack_h2(acc1[m][nt][2], acc1[m][nt][3]), bb));
                    }
                }
            }
            __syncthreads();

            // GEMM2 partial: h3 += h2s @ W2[h*128.., :]; warp: 32 rows x 32 cols
#pragma unroll 2
            for (int kt2 = 0; kt2 < 8; kt2++){
                uint4 a0 = *(const uint4*)(buf + (kt2*8 + 2*wr    )*128 + lane*4);
                uint4 a1 = *(const uint4*)(buf + (kt2*8 + 2*wr + 1)*128 + lane*4);
                int gk = h*8 + kt2;                        // global 16-k tile
#pragma unroll
                for (int nt = 0; nt < 4; nt++){
                    int n = wc*4 + nt;                     // global 8-col tile
                    uint2 b = *(const uint2*)(sW2 + (((gk >> 2)*4 + (gk & 3))*16 + n)*64 + lane*2);
                    mma16(acc2[0][nt], a0, b);
                    mma16(acc2[1][nt], a1, b);
                }
            }
            __syncthreads();   // WAR: buf rewritten next sweep (or s_kern later)
        }

        // ---- epilogue2: h3 = gelu(acc2 + b2) -> sH1 image ----
        {
#pragma unroll
            for (int m = 0; m < 2; m++){
                int r0 = 32*wr + 16*m + g;
#pragma unroll
                for (int nt = 0; nt < 4; nt++){
                    int cg = wc*32 + nt*8 + 2*q;
                    uint32_t bb = sb2h[cg >> 1];
                    sH1[aidx(r0,     cg)] = gelu_h2(hadd2u(
                        pack_h2(acc2[m][nt][0], acc2[m][nt][1]), bb));
                    sH1[aidx(r0 + 8, cg)] = gelu_h2(hadd2u(
                        pack_h2(acc2[m][nt][2], acc2[m][nt][3]), bb));
                }
            }
        }
        __syncthreads();

        // ---- f_y prefetch (overlaps GEMM3): warp w owns rr = w, all 4 t ----
        float fyv[4][8];
#pragma unroll
        for (int t2 = 0; t2 < 4; t2++)
#pragma unroll
            for (int j = 0; j < 8; j++)
                fyv[t2][j] = fy[((size_t)t2*NY + s_nbr[w*8 + j])*NC + lane];

        // ---- GEMM3: kern[128x32] = h3 @ W3; warp: 16 rows x 16 cols ----
        float acc3[2][4];
#pragma unroll
        for (int n = 0; n < 2; n++)
#pragma unroll
            for (int r = 0; r < 4; r++) acc3[n][r] = 0.f;
#pragma unroll 2
        for (int kt = 0; kt < 8; kt++){
            uint4 a = *(const uint4*)(sH1 + (kt*8 + wr3)*128 + lane*4);
#pragma unroll
            for (int nt = 0; nt < 2; nt++){
                uint2 b = *(const uint2*)(sW3 + (kt*4 + wc3*2 + nt)*64 + lane*2);
                mma16(acc3[nt], a, b);
            }
        }
        float* s_kern = (float*)(sm + OFF_H2);    // 128x33 fp32 (over buf)
        {
            int r0 = 16*wr3 + g;
#pragma unroll
            for (int nt = 0; nt < 2; nt++){
                int c = wc3*16 + nt*8 + 2*q;
                float bb0 = sb3[c], bb1 = sb3[c + 1];
                s_kern[r0*33 + c]           = acc3[nt][0] + bb0;
                s_kern[r0*33 + c + 1]       = acc3[nt][1] + bb1;
                s_kern[(r0 + 8)*33 + c]     = acc3[nt][2] + bb0;
                s_kern[(r0 + 8)*33 + c + 1] = acc3[nt][3] + bb1;
            }
        }
        __syncthreads();

        // ---- reduction: kern loaded once into regs, reused for all 4 t ----
        {
            float k8[8];
#pragma unroll
            for (int j = 0; j < 8; j++) k8[j] = s_kern[(w*8 + j)*33 + lane];
#pragma unroll
            for (int t2 = 0; t2 < 4; t2++){
                float acc = 0.f;
#pragma unroll
                for (int j = 0; j < 8; j++)
                    acc = fmaf(k8[j], fyv[t2][j], acc);
                out[((size_t)t2*NX + xbase + w)*NC + lane] = acc;
            }
        }
        __syncthreads();   // protect s_nbr / sH1 / s_kern before next tile
    }
}

// ---------------- launch ----------------
extern "C" void kernel_launch(void* const* d_in, const int* in_sizes, int n_in,
                              void* d_out, int out_size)
{
    const float* y  = (const float*)d_in[0];
    const float* x  = (const float*)d_in[1];
    const float* fy = (const float*)d_in[2];
    const int*   nbr = (const int*)d_in[3];
    const float* W0 = (const float*)d_in[4];  const float* b0 = (const float*)d_in[5];
    const float* W1 = (const float*)d_in[6];  const float* b1 = (const float*)d_in[7];
    const float* W2 = (const float*)d_in[8];  const float* b2 = (const float*)d_in[9];
    const float* W3 = (const float*)d_in[10]; const float* b3 = (const float*)d_in[11];
    float* out = (float*)d_out;

    int nyb = (NY + 127)/128, nxb = (NX + 127)/128;
    cudaFuncSetAttribute(prep_kernel,
                         cudaFuncAttributeMaxDynamicSharedMemorySize, PRE_SMEM);
    prep_kernel<<<nyb + nxb + 136, 256, PRE_SMEM>>>(y, x, W0, b0, W1, W2, W3);

    cudaFuncSetAttribute(edge_kernel,
                         cudaFuncAttributeMaxDynamicSharedMemorySize, SMEM_BYTES);
    edge_kernel<<<152, 512, SMEM_BYTES>>>(nbr, fy, b1, b2, b3, out);
}